// round 3
// baseline (speedup 1.0000x reference)
#include <cuda_runtime.h>

#define NN 50000
#define EE 600000
#define ET 650000   // edges + self loops
#define NG 64
#define NC 10

// ---------------- scratch (device globals; no allocation allowed) ----------
__device__ float g_xlr1[(size_t)NN * 256];  // [n][0:128]=x@Wl1, [128:256]=x@Wr1
__device__ float g_h1  [(size_t)NN * 128];  // agg1 -> +b1,elu in place -> h1
__device__ float g_xlr2[(size_t)NN * 128];  // [n][0:64]=h1@Wl2, [64:128]=h1@Wr2
__device__ float g_agg2[(size_t)NN * 64];
__device__ float g_p1  [(size_t)ET * 2];
__device__ float g_den1[(size_t)NN * 2];
__device__ float g_p2  [ET];
__device__ float g_den2[NN];
__device__ float g_pool[NG * 64];
__device__ float g_cnt [NG];
__device__ int   g_src [ET];
__device__ int   g_dst [ET];
__device__ int   g_batch[NN];
__device__ int   g_is64;

// ---------------- dtype detection -----------------------------------------
// int64 little-endian values < 2^31 have zero high words at odd int32
// positions; int32 data has real node ids there. 4096 samples -> certain.
__global__ void detect64(const int* __restrict__ ei)
{
    __shared__ int nz;
    if (threadIdx.x == 0) nz = 0;
    __syncthreads();
    int local = 0;
    for (int i = threadIdx.x; i < 4096; i += blockDim.x)
        if (ei[2 * i + 1] != 0) local = 1;
    if (local) atomicOr(&nz, 1);
    __syncthreads();
    if (threadIdx.x == 0) g_is64 = nz ? 0 : 1;
}

// materialize int32 src/dst (+self loops) and batch; clamp for IMA safety
__global__ void prep_idx(const int* __restrict__ ei, const int* __restrict__ bat)
{
    const int T = gridDim.x * blockDim.x;
    const int t = blockIdx.x * blockDim.x + threadIdx.x;
    const bool is64 = (g_is64 != 0);
    for (int i = t; i < EE; i += T) {
        int s = is64 ? ei[2 * i]            : ei[i];
        int d = is64 ? ei[2 * (EE + i)]     : ei[EE + i];
        g_src[i] = min(max(s, 0), NN - 1);
        g_dst[i] = min(max(d, 0), NN - 1);
    }
    for (int i = t; i < NN; i += T) {
        g_src[EE + i] = i;
        g_dst[EE + i] = i;
        int b = is64 ? bat[2 * i] : bat[i];
        g_batch[i] = min(max(b, 0), NG - 1);
    }
}

// ---------------- zero scratch ---------------------------------------------
__global__ void zero_scratch()
{
    const size_t T = (size_t)gridDim.x * blockDim.x;
    const size_t t = (size_t)blockIdx.x * blockDim.x + threadIdx.x;
    float4 z = make_float4(0.f, 0.f, 0.f, 0.f);
    for (size_t i = t; i < (size_t)NN * 128 / 4; i += T) ((float4*)g_h1)[i] = z;
    for (size_t i = t; i < (size_t)NN * 64 / 4;  i += T) ((float4*)g_agg2)[i] = z;
    for (size_t i = t; i < (size_t)NN / 2;       i += T) ((float4*)g_den1)[i] = z;
    for (size_t i = t; i < (size_t)NN;           i += T) g_den2[i] = 0.f;
    for (size_t i = t; i < (size_t)NG * 64;      i += T) g_pool[i] = 0.f;
    for (size_t i = t; i < (size_t)NG;           i += T) g_cnt[i] = 0.f;
}

// ---------------- SGEMM ----------------------------------------------------
template<int BM, int BN, int BK, int TM, int TN, bool A_IS_H1, bool C_IS_L1>
__global__ __launch_bounds__((BM / TM) * (BN / TN))
void sgemm2(const float* __restrict__ Ain, const float* __restrict__ B0,
            const float* __restrict__ B1, int M, int K, int ldc)
{
    constexpr int THREADS = (BM / TM) * (BN / TN);
    const float* __restrict__ A = A_IS_H1 ? (const float*)g_h1 : Ain;
    float* __restrict__ C = C_IS_L1 ? (float*)g_xlr1 : (float*)g_xlr2;
    const float* B = (blockIdx.y == 0) ? B0 : B1;
    const int colOff = blockIdx.y * BN;

    __shared__ float As[BK][BM];
    __shared__ float Bs[BK][BN];

    const int tid = threadIdx.x;
    const int tx = tid % (BN / TN);
    const int ty = tid / (BN / TN);
    const int rowBase = blockIdx.x * BM;

    float acc[TM][TN];
#pragma unroll
    for (int i = 0; i < TM; i++)
#pragma unroll
        for (int j = 0; j < TN; j++) acc[i][j] = 0.f;

    for (int kt = 0; kt < K; kt += BK) {
        constexpr int A_F4 = BM * BK / 4;
#pragma unroll
        for (int i = tid; i < A_F4; i += THREADS) {
            int r  = i / (BK / 4);
            int kk = (i % (BK / 4)) * 4;
            int grow = rowBase + r;
            float4 v = make_float4(0.f, 0.f, 0.f, 0.f);
            if (grow < M)
                v = *(const float4*)(A + (size_t)grow * K + kt + kk);
            As[kk + 0][r] = v.x; As[kk + 1][r] = v.y;
            As[kk + 2][r] = v.z; As[kk + 3][r] = v.w;
        }
        constexpr int B_F4 = BK * BN / 4;
#pragma unroll
        for (int i = tid; i < B_F4; i += THREADS) {
            int r  = i / (BN / 4);
            int cc = (i % (BN / 4)) * 4;
            *(float4*)&Bs[r][cc] = *(const float4*)(B + (size_t)(kt + r) * BN + cc);
        }
        __syncthreads();

#pragma unroll
        for (int k = 0; k < BK; k++) {
            float a[TM], b[TN];
#pragma unroll
            for (int i = 0; i < TM; i++) a[i] = As[k][ty * TM + i];
#pragma unroll
            for (int j = 0; j < TN; j++) b[j] = Bs[k][tx * TN + j];
#pragma unroll
            for (int i = 0; i < TM; i++)
#pragma unroll
                for (int j = 0; j < TN; j++)
                    acc[i][j] = fmaf(a[i], b[j], acc[i][j]);
        }
        __syncthreads();
    }

#pragma unroll
    for (int i = 0; i < TM; i++) {
        int r = rowBase + ty * TM + i;
        if (r >= M) continue;
        float* cp = C + (size_t)r * ldc + colOff + tx * TN;
#pragma unroll
        for (int j = 0; j < TN; j++) cp[j] = acc[i][j];
    }
}

// ---------------- edge kernels ---------------------------------------------
// layer 1 attention: e_h = att1_h . lrelu(xl[src] + xr[dst]);  p = exp(e)
__global__ __launch_bounds__(256)
void edge1_att(const float* __restrict__ att)
{
    int w = (blockIdx.x * blockDim.x + threadIdx.x) >> 5;
    if (w >= ET) return;
    int lane = threadIdx.x & 31;
    int s = g_src[w], d = g_dst[w];

    const float* xl = g_xlr1 + (size_t)s * 256;
    const float* xr = g_xlr1 + (size_t)d * 256 + 128;
    float p0 = 0.f, p1 = 0.f;
#pragma unroll
    for (int i = 0; i < 4; i++) {
        int c = lane + 32 * i;
        float m = xl[c] + xr[c];
        m = (m > 0.f) ? m : 0.2f * m;
        float v = m * __ldg(&att[c]);
        if (i < 2) p0 += v; else p1 += v;
    }
#pragma unroll
    for (int o = 16; o > 0; o >>= 1) {
        p0 += __shfl_xor_sync(0xffffffffu, p0, o);
        p1 += __shfl_xor_sync(0xffffffffu, p1, o);
    }
    if (lane == 0) {
        float e0 = expf(p0), e1 = expf(p1);
        g_p1[(size_t)w * 2]     = e0;
        g_p1[(size_t)w * 2 + 1] = e1;
        atomicAdd(&g_den1[d * 2],     e0);
        atomicAdd(&g_den1[d * 2 + 1], e1);
    }
}

__global__ __launch_bounds__(256)
void edge1_agg()
{
    int w = (blockIdx.x * blockDim.x + threadIdx.x) >> 5;
    if (w >= ET) return;
    int lane = threadIdx.x & 31;
    int s = g_src[w], d = g_dst[w];

    float a0 = g_p1[(size_t)w * 2]     / g_den1[d * 2];
    float a1 = g_p1[(size_t)w * 2 + 1] / g_den1[d * 2 + 1];
    const float* xl = g_xlr1 + (size_t)s * 256;
    float* out = g_h1 + (size_t)d * 128;
#pragma unroll
    for (int i = 0; i < 4; i++) {
        int c = lane + 32 * i;
        atomicAdd(&out[c], ((i < 2) ? a0 : a1) * xl[c]);
    }
}

__global__ __launch_bounds__(256)
void node1_elu(const float* __restrict__ b1)
{
    size_t idx = (size_t)blockIdx.x * blockDim.x + threadIdx.x;
    if (idx >= (size_t)NN * 128) return;
    float v = g_h1[idx] + __ldg(&b1[idx & 127]);
    g_h1[idx] = (v > 0.f) ? v : expm1f(v);
}

// layer 2: 1 head, 64 channels
__global__ __launch_bounds__(256)
void edge2_att(const float* __restrict__ att)
{
    int w = (blockIdx.x * blockDim.x + threadIdx.x) >> 5;
    if (w >= ET) return;
    int lane = threadIdx.x & 31;
    int s = g_src[w], d = g_dst[w];

    const float* xl = g_xlr2 + (size_t)s * 128;
    const float* xr = g_xlr2 + (size_t)d * 128 + 64;
    float p = 0.f;
#pragma unroll
    for (int i = 0; i < 2; i++) {
        int c = lane + 32 * i;
        float m = xl[c] + xr[c];
        m = (m > 0.f) ? m : 0.2f * m;
        p += m * __ldg(&att[c]);
    }
#pragma unroll
    for (int o = 16; o > 0; o >>= 1)
        p += __shfl_xor_sync(0xffffffffu, p, o);
    if (lane == 0) {
        float e = expf(p);
        g_p2[w] = e;
        atomicAdd(&g_den2[d], e);
    }
}

__global__ __launch_bounds__(256)
void edge2_agg()
{
    int w = (blockIdx.x * blockDim.x + threadIdx.x) >> 5;
    if (w >= ET) return;
    int lane = threadIdx.x & 31;
    int s = g_src[w], d = g_dst[w];

    float a = g_p2[w] / g_den2[d];
    const float* xl = g_xlr2 + (size_t)s * 128;
    float* out = g_agg2 + (size_t)d * 64;
#pragma unroll
    for (int i = 0; i < 2; i++) {
        int c = lane + 32 * i;
        atomicAdd(&out[c], a * xl[c]);
    }
}

__global__ __launch_bounds__(256)
void node2_pool(const float* __restrict__ b2)
{
    size_t idx = (size_t)blockIdx.x * blockDim.x + threadIdx.x;
    if (idx >= (size_t)NN * 64) return;
    int n = (int)(idx >> 6);
    int c = (int)(idx & 63);
    float v = g_agg2[idx] + __ldg(&b2[c]);
    v = (v > 0.f) ? v : expm1f(v);
    int g = g_batch[n];
    atomicAdd(&g_pool[g * 64 + c], v);
    if (c == 0) atomicAdd(&g_cnt[g], 1.0f);
}

__global__ void final_lin(const float* __restrict__ Wlin,
                          const float* __restrict__ blin,
                          float* __restrict__ out)
{
    int tid = threadIdx.x;
    if (tid >= NG * NC) return;
    int g = tid / NC, j = tid % NC;
    float cnt = g_cnt[g];
    if (cnt < 1.f) cnt = 1.f;
    float inv = 1.f / cnt;
    float acc = blin[j];
#pragma unroll
    for (int c = 0; c < 64; c++)
        acc = fmaf(g_pool[g * 64 + c] * inv, Wlin[c * NC + j], acc);
    out[tid] = acc;
}

// ---------------- launch (ONLY kernel launches) -----------------------------
extern "C" void kernel_launch(void* const* d_in, const int* in_sizes, int n_in,
                              void* d_out, int out_size)
{
    const float* x     = (const float*)d_in[0];
    const int*   ei    = (const int*)d_in[1];    // int32 view; dtype detected
    const int*   batch = (const int*)d_in[2];
    const float* Wl1   = (const float*)d_in[3];
    const float* Wr1   = (const float*)d_in[4];
    const float* att1  = (const float*)d_in[5];
    const float* b1    = (const float*)d_in[6];
    const float* Wl2   = (const float*)d_in[7];
    const float* Wr2   = (const float*)d_in[8];
    const float* att2  = (const float*)d_in[9];
    const float* b2    = (const float*)d_in[10];
    const float* Wlin  = (const float*)d_in[11];
    const float* blin  = (const float*)d_in[12];
    float*       out   = (float*)d_out;

    const int MBLK = (NN + 127) / 128;         // 391
    const int EBLK = (ET + 7) / 8;             // 81250 (8 warps/block)

    detect64<<<1, 256>>>(ei);
    prep_idx<<<1024, 256>>>(ei, batch);
    zero_scratch<<<512, 256>>>();

    // layer 1 linear: xlr1[:,0:128] = x@Wl1 ; [:,128:256] = x@Wr1
    sgemm2<128, 128, 8, 8, 8, false, true><<<dim3(MBLK, 2), 256>>>(
        x, Wl1, Wr1, NN, 128, 256);

    edge1_att<<<EBLK, 256>>>(att1);
    edge1_agg<<<EBLK, 256>>>();
    node1_elu<<<(NN * 128 + 255) / 256, 256>>>(b1);

    // layer 2 linear: xlr2[:,0:64] = h1@Wl2 ; [:,64:128] = h1@Wr2
    sgemm2<128, 64, 8, 8, 4, true, false><<<dim3(MBLK, 2), 256>>>(
        nullptr, Wl2, Wr2, NN, 128, 128);

    edge2_att<<<EBLK, 256>>>(att2);
    edge2_agg<<<EBLK, 256>>>();
    node2_pool<<<(NN * 64 + 255) / 256, 256>>>(b2);

    final_lin<<<1, NG * NC>>>(Wlin, blin, out);
}

// round 4
// speedup vs baseline: 1.4322x; 1.4322x over previous
#include <cuda_runtime.h>

#define NN 50000
#define EE 600000
#define ET 650000   // edges + self loops
#define NG 64
#define NC 10

// ---------------- scratch (device globals) ---------------------------------
__device__ float g_xlr1[(size_t)NN * 256];  // [n][0:128]=x@Wl1, [128:256]=x@Wr1
__device__ float g_h1  [(size_t)NN * 128];  // layer-1 output (elu applied)
__device__ float g_xlr2[(size_t)NN * 128];  // [n][0:64]=h1@Wl2, [64:128]=h1@Wr2
__device__ float g_p1  [(size_t)ET * 2];    // exp(e) per csr slot (2 heads)
__device__ float g_p2  [ET];
__device__ int   g_src [ET];
__device__ int   g_dst [ET];
__device__ int   g_csrc[ET];                // src ids in CSR-by-dst order
__device__ int   g_deg [NN];
__device__ int   g_row [NN + 1];
__device__ int   g_cur [NN];
__device__ int   g_batch[NN];
__device__ int   g_gcnt[NG];
__device__ float g_pool[NG * 64];
__device__ int   g_is64;

// ---------------- dtype detection ------------------------------------------
__global__ void detect64(const int* __restrict__ ei)
{
    __shared__ int nz;
    if (threadIdx.x == 0) nz = 0;
    __syncthreads();
    int local = 0;
    for (int i = threadIdx.x; i < 4096; i += blockDim.x)
        if (ei[2 * i + 1] != 0) local = 1;
    if (local) atomicOr(&nz, 1);
    __syncthreads();
    if (threadIdx.x == 0) g_is64 = nz ? 0 : 1;
}

__global__ void zero_small()
{
    const int T = gridDim.x * blockDim.x;
    const int t = blockIdx.x * blockDim.x + threadIdx.x;
    for (int i = t; i < NN; i += T) g_deg[i] = 0;
    for (int i = t; i < NG * 64; i += T) g_pool[i] = 0.f;
    for (int i = t; i < NG; i += T) g_gcnt[i] = 0;
}

// decode (+clamp) edges & batch, histogram dst degree and graph counts
__global__ void prep_idx(const int* __restrict__ ei, const int* __restrict__ bat)
{
    const int T = gridDim.x * blockDim.x;
    const int t = blockIdx.x * blockDim.x + threadIdx.x;
    const bool is64 = (g_is64 != 0);
    for (int i = t; i < EE; i += T) {
        int s = is64 ? ei[2 * i]        : ei[i];
        int d = is64 ? ei[2 * (EE + i)] : ei[EE + i];
        s = min(max(s, 0), NN - 1);
        d = min(max(d, 0), NN - 1);
        g_src[i] = s;
        g_dst[i] = d;
        atomicAdd(&g_deg[d], 1);
    }
    for (int i = t; i < NN; i += T) {
        g_src[EE + i] = i;
        g_dst[EE + i] = i;
        atomicAdd(&g_deg[i], 1);
        int b = is64 ? bat[2 * i] : bat[i];
        b = min(max(b, 0), NG - 1);
        g_batch[i] = b;
        atomicAdd(&g_gcnt[b], 1);
    }
}

// exclusive scan of g_deg -> g_row / g_cur  (single block, 1024 threads)
__global__ __launch_bounds__(1024) void scan_deg()
{
    __shared__ int part[1024];
    const int t = threadIdx.x;
    const int CH = (NN + 1023) / 1024;   // 49
    const int base = t * CH;
    int s = 0;
    for (int i = 0; i < CH; i++) {
        int idx = base + i;
        if (idx < NN) s += g_deg[idx];
    }
    part[t] = s;
    __syncthreads();
    for (int o = 1; o < 1024; o <<= 1) {
        int v = (t >= o) ? part[t - o] : 0;
        __syncthreads();
        part[t] += v;
        __syncthreads();
    }
    int run = (t == 0) ? 0 : part[t - 1];
    for (int i = 0; i < CH; i++) {
        int idx = base + i;
        if (idx < NN) {
            g_row[idx] = run;
            g_cur[idx] = run;
            run += g_deg[idx];
        }
    }
    if (t == 1023) g_row[NN] = ET;
}

__global__ void scatter_csr()
{
    const int T = gridDim.x * blockDim.x;
    const int t = blockIdx.x * blockDim.x + threadIdx.x;
    for (int i = t; i < ET; i += T) {
        int d = g_dst[i];
        int pos = atomicAdd(&g_cur[d], 1);
        g_csrc[pos] = g_src[i];
    }
}

// ---------------- SGEMM ----------------------------------------------------
template<int BM, int BN, int BK, int TM, int TN, bool A_IS_H1, bool C_IS_L1>
__global__ __launch_bounds__((BM / TM) * (BN / TN))
void sgemm2(const float* __restrict__ Ain, const float* __restrict__ B0,
            const float* __restrict__ B1, int M, int K, int ldc)
{
    constexpr int THREADS = (BM / TM) * (BN / TN);
    const float* __restrict__ A = A_IS_H1 ? (const float*)g_h1 : Ain;
    float* __restrict__ C = C_IS_L1 ? (float*)g_xlr1 : (float*)g_xlr2;
    const float* B = (blockIdx.y == 0) ? B0 : B1;
    const int colOff = blockIdx.y * BN;

    __shared__ float As[BK][BM];
    __shared__ float Bs[BK][BN];

    const int tid = threadIdx.x;
    const int tx = tid % (BN / TN);
    const int ty = tid / (BN / TN);
    const int rowBase = blockIdx.x * BM;

    float acc[TM][TN];
#pragma unroll
    for (int i = 0; i < TM; i++)
#pragma unroll
        for (int j = 0; j < TN; j++) acc[i][j] = 0.f;

    for (int kt = 0; kt < K; kt += BK) {
        constexpr int A_F4 = BM * BK / 4;
#pragma unroll
        for (int i = tid; i < A_F4; i += THREADS) {
            int r  = i / (BK / 4);
            int kk = (i % (BK / 4)) * 4;
            int grow = rowBase + r;
            float4 v = make_float4(0.f, 0.f, 0.f, 0.f);
            if (grow < M)
                v = *(const float4*)(A + (size_t)grow * K + kt + kk);
            As[kk + 0][r] = v.x; As[kk + 1][r] = v.y;
            As[kk + 2][r] = v.z; As[kk + 3][r] = v.w;
        }
        constexpr int B_F4 = BK * BN / 4;
#pragma unroll
        for (int i = tid; i < B_F4; i += THREADS) {
            int r  = i / (BN / 4);
            int cc = (i % (BN / 4)) * 4;
            *(float4*)&Bs[r][cc] = *(const float4*)(B + (size_t)(kt + r) * BN + cc);
        }
        __syncthreads();

#pragma unroll
        for (int k = 0; k < BK; k++) {
            float a[TM], b[TN];
#pragma unroll
            for (int i = 0; i < TM; i++) a[i] = As[k][ty * TM + i];
#pragma unroll
            for (int j = 0; j < TN; j++) b[j] = Bs[k][tx * TN + j];
#pragma unroll
            for (int i = 0; i < TM; i++)
#pragma unroll
                for (int j = 0; j < TN; j++)
                    acc[i][j] = fmaf(a[i], b[j], acc[i][j]);
        }
        __syncthreads();
    }

#pragma unroll
    for (int i = 0; i < TM; i++) {
        int r = rowBase + ty * TM + i;
        if (r >= M) continue;
        float* cp = C + (size_t)r * ldc + colOff + tx * TN;
#pragma unroll
        for (int j = 0; j < TN; j++) cp[j] = acc[i][j];
    }
}

// ---------------- fused GAT layer 1 (warp per dst node, no atomics) --------
__global__ __launch_bounds__(256)
void gat1(const float* __restrict__ att, const float* __restrict__ b1)
{
    int w = (blockIdx.x * blockDim.x + threadIdx.x) >> 5;
    if (w >= NN) return;
    const int lane = threadIdx.x & 31;
    const int e0 = g_row[w], e1 = g_row[w + 1];

    float xr[4], a[4];
    const float* xrp = g_xlr1 + (size_t)w * 256 + 128;
#pragma unroll
    for (int i = 0; i < 4; i++) {
        xr[i] = xrp[lane + 32 * i];
        a[i]  = __ldg(&att[lane + 32 * i]);
    }

    float den0 = 0.f, den1 = 0.f;
    for (int e = e0; e < e1; e++) {
        int s = g_csrc[e];
        const float* xlp = g_xlr1 + (size_t)s * 256;
        float p0 = 0.f, p1 = 0.f;
#pragma unroll
        for (int i = 0; i < 4; i++) {
            float m = xlp[lane + 32 * i] + xr[i];
            m = (m > 0.f) ? m : 0.2f * m;
            float v = m * a[i];
            if (i < 2) p0 += v; else p1 += v;
        }
#pragma unroll
        for (int o = 16; o > 0; o >>= 1) {
            p0 += __shfl_xor_sync(0xffffffffu, p0, o);
            p1 += __shfl_xor_sync(0xffffffffu, p1, o);
        }
        float q0 = expf(p0), q1 = expf(p1);   // identical on all lanes
        den0 += q0; den1 += q1;
        if (lane == 0) ((float2*)g_p1)[e] = make_float2(q0, q1);
    }
    float r0 = 1.f / den0, r1 = 1.f / den1;

    float out[4] = {0.f, 0.f, 0.f, 0.f};
    for (int e = e0; e < e1; e++) {
        int s = g_csrc[e];
        const float* xlp = g_xlr1 + (size_t)s * 256;
        float2 q = ((const float2*)g_p1)[e];  // same addr all lanes: broadcast
        float a0 = q.x * r0, a1 = q.y * r1;
#pragma unroll
        for (int i = 0; i < 4; i++)
            out[i] = fmaf((i < 2) ? a0 : a1, xlp[lane + 32 * i], out[i]);
    }
#pragma unroll
    for (int i = 0; i < 4; i++) {
        int c = lane + 32 * i;
        float v = out[i] + __ldg(&b1[c]);
        g_h1[(size_t)w * 128 + c] = (v > 0.f) ? v : expm1f(v);
    }
}

// ---------------- fused GAT layer 2 + pool (warp per dst node) -------------
__global__ __launch_bounds__(256)
void gat2(const float* __restrict__ att, const float* __restrict__ b2)
{
    int w = (blockIdx.x * blockDim.x + threadIdx.x) >> 5;
    if (w >= NN) return;
    const int lane = threadIdx.x & 31;
    const int e0 = g_row[w], e1 = g_row[w + 1];

    float xr[2], a[2];
    const float* xrp = g_xlr2 + (size_t)w * 128 + 64;
#pragma unroll
    for (int i = 0; i < 2; i++) {
        xr[i] = xrp[lane + 32 * i];
        a[i]  = __ldg(&att[lane + 32 * i]);
    }

    float den = 0.f;
    for (int e = e0; e < e1; e++) {
        int s = g_csrc[e];
        const float* xlp = g_xlr2 + (size_t)s * 128;
        float p = 0.f;
#pragma unroll
        for (int i = 0; i < 2; i++) {
            float m = xlp[lane + 32 * i] + xr[i];
            m = (m > 0.f) ? m : 0.2f * m;
            p += m * a[i];
        }
#pragma unroll
        for (int o = 16; o > 0; o >>= 1)
            p += __shfl_xor_sync(0xffffffffu, p, o);
        float q = expf(p);
        den += q;
        if (lane == 0) g_p2[e] = q;
    }
    float r = 1.f / den;

    float out[2] = {0.f, 0.f};
    for (int e = e0; e < e1; e++) {
        int s = g_csrc[e];
        const float* xlp = g_xlr2 + (size_t)s * 128;
        float al = g_p2[e] * r;
#pragma unroll
        for (int i = 0; i < 2; i++)
            out[i] = fmaf(al, xlp[lane + 32 * i], out[i]);
    }
    const int g = g_batch[w];
#pragma unroll
    for (int i = 0; i < 2; i++) {
        int c = lane + 32 * i;
        float v = out[i] + __ldg(&b2[c]);
        v = (v > 0.f) ? v : expm1f(v);
        atomicAdd(&g_pool[g * 64 + c], v);
    }
}

__global__ void final_lin(const float* __restrict__ Wlin,
                          const float* __restrict__ blin,
                          float* __restrict__ out)
{
    int tid = threadIdx.x;
    if (tid >= NG * NC) return;
    int g = tid / NC, j = tid % NC;
    float inv = 1.f / fmaxf((float)g_gcnt[g], 1.f);
    float acc = blin[j];
#pragma unroll
    for (int c = 0; c < 64; c++)
        acc = fmaf(g_pool[g * 64 + c] * inv, Wlin[c * NC + j], acc);
    out[tid] = acc;
}

// ---------------- launch (ONLY kernel launches) -----------------------------
extern "C" void kernel_launch(void* const* d_in, const int* in_sizes, int n_in,
                              void* d_out, int out_size)
{
    const float* x     = (const float*)d_in[0];
    const int*   ei    = (const int*)d_in[1];
    const int*   batch = (const int*)d_in[2];
    const float* Wl1   = (const float*)d_in[3];
    const float* Wr1   = (const float*)d_in[4];
    const float* att1  = (const float*)d_in[5];
    const float* b1    = (const float*)d_in[6];
    const float* Wl2   = (const float*)d_in[7];
    const float* Wr2   = (const float*)d_in[8];
    const float* att2  = (const float*)d_in[9];
    const float* b2    = (const float*)d_in[10];
    const float* Wlin  = (const float*)d_in[11];
    const float* blin  = (const float*)d_in[12];
    float*       out   = (float*)d_out;

    const int MBLK = (NN + 127) / 128;        // 391
    const int NWBLK = (NN * 32 + 255) / 256;  // 6250 (warp per node)

    detect64<<<1, 256>>>(ei);
    zero_small<<<64, 256>>>();
    prep_idx<<<512, 256>>>(ei, batch);
    scan_deg<<<1, 1024>>>();
    scatter_csr<<<512, 256>>>();

    sgemm2<128, 128, 8, 8, 8, false, true><<<dim3(MBLK, 2), 256>>>(
        x, Wl1, Wr1, NN, 128, 256);
    gat1<<<NWBLK, 256>>>(att1, b1);

    sgemm2<128, 64, 8, 8, 4, true, false><<<dim3(MBLK, 2), 256>>>(
        nullptr, Wl2, Wr2, NN, 128, 128);
    gat2<<<NWBLK, 256>>>(att2, b2);

    final_lin<<<1, NG * NC>>>(Wlin, blin, out);
}

// round 6
// speedup vs baseline: 1.9394x; 1.3541x over previous
#include <cuda_runtime.h>

#define NN 50000
#define EE 600000
#define ET 650000   // edges + self loops
#define NG 64
#define NC 10
#define SCAN_B ((NN + 255) / 256)   // 196

// ---------------- scratch (device globals) ---------------------------------
__device__ float g_xlr1[(size_t)NN * 256];  // [n][0:128]=x@Wl1, [128:256]=x@Wr1
__device__ float g_h1  [(size_t)NN * 128];  // layer-1 output (elu applied)
__device__ float g_xlr2[(size_t)NN * 128];  // [n][0:64]=h1@Wl2, [64:128]=h1@Wr2
__device__ int   g_csrc[ET];                // src ids in CSR-by-dst order
__device__ int   g_deg [NN];
__device__ int   g_row [NN + 1];
__device__ int   g_cur [NN];
__device__ int   g_bsum[SCAN_B];
__device__ int   g_boff[SCAN_B];
__device__ int   g_batch[NN];
__device__ int   g_gcnt[NG];
__device__ float g_pool[NG * 64];
__device__ int   g_is64;

// ---------------- dtype detection ------------------------------------------
__global__ void detect64(const int* __restrict__ ei)
{
    __shared__ int nz;
    if (threadIdx.x == 0) nz = 0;
    __syncthreads();
    int local = 0;
    for (int i = threadIdx.x; i < 4096; i += blockDim.x)
        if (ei[2 * i + 1] != 0) local = 1;
    if (local) atomicOr(&nz, 1);
    __syncthreads();
    if (threadIdx.x == 0) g_is64 = nz ? 0 : 1;
}

__global__ void zero_small()
{
    const int T = gridDim.x * blockDim.x;
    const int t = blockIdx.x * blockDim.x + threadIdx.x;
    for (int i = t; i < NN; i += T) g_deg[i] = 0;
    for (int i = t; i < NG * 64; i += T) g_pool[i] = 0.f;
    for (int i = t; i < NG; i += T) g_gcnt[i] = 0;
}

// decode batch + histogram dst degree + graph counts (shared-mem binned)
__global__ __launch_bounds__(256)
void prep_idx(const int* __restrict__ ei, const int* __restrict__ bat)
{
    __shared__ int bins[NG];
    for (int i = threadIdx.x; i < NG; i += blockDim.x) bins[i] = 0;
    __syncthreads();

    const int T = gridDim.x * blockDim.x;
    const int t = blockIdx.x * blockDim.x + threadIdx.x;
    const bool is64 = (g_is64 != 0);
    for (int i = t; i < EE; i += T) {
        int d = is64 ? ei[2 * (EE + i)] : ei[EE + i];
        d = min(max(d, 0), NN - 1);
        atomicAdd(&g_deg[d], 1);
    }
    for (int i = t; i < NN; i += T) {
        atomicAdd(&g_deg[i], 1);             // self loop
        int b = is64 ? bat[2 * i] : bat[i];
        b = min(max(b, 0), NG - 1);
        g_batch[i] = b;
        atomicAdd(&bins[b], 1);
    }
    __syncthreads();
    for (int i = threadIdx.x; i < NG; i += blockDim.x)
        if (bins[i]) atomicAdd(&g_gcnt[i], bins[i]);
}

// ---------------- decoupled exclusive scan of g_deg ------------------------
__global__ __launch_bounds__(256) void deg_partial()
{
    __shared__ int s[256];
    int idx = blockIdx.x * 256 + threadIdx.x;
    int v = (idx < NN) ? g_deg[idx] : 0;
    s[threadIdx.x] = v;
    __syncthreads();
#pragma unroll
    for (int o = 128; o > 0; o >>= 1) {
        if (threadIdx.x < o) s[threadIdx.x] += s[threadIdx.x + o];
        __syncthreads();
    }
    if (threadIdx.x == 0) g_bsum[blockIdx.x] = s[0];
}

__global__ __launch_bounds__(256) void scan_bsums()
{
    __shared__ int s[256];
    int t = threadIdx.x;
    int v = (t < SCAN_B) ? g_bsum[t] : 0;
    s[t] = v;
    __syncthreads();
#pragma unroll
    for (int o = 1; o < 256; o <<= 1) {
        int u = (t >= o) ? s[t - o] : 0;
        __syncthreads();
        s[t] += u;
        __syncthreads();
    }
    if (t < SCAN_B) g_boff[t] = s[t] - v;   // exclusive
}

__global__ __launch_bounds__(256) void scan_final()
{
    __shared__ int s[256];
    int t = threadIdx.x;
    int idx = blockIdx.x * 256 + t;
    int v = (idx < NN) ? g_deg[idx] : 0;
    s[t] = v;
    __syncthreads();
#pragma unroll
    for (int o = 1; o < 256; o <<= 1) {
        int u = (t >= o) ? s[t - o] : 0;
        __syncthreads();
        s[t] += u;
        __syncthreads();
    }
    int excl = s[t] - v + g_boff[blockIdx.x];
    if (idx < NN) { g_row[idx] = excl; g_cur[idx] = excl; }
    if (idx == NN - 1) g_row[NN] = ET;
}

__global__ void scatter_csr(const int* __restrict__ ei)
{
    const int T = gridDim.x * blockDim.x;
    const int t = blockIdx.x * blockDim.x + threadIdx.x;
    const bool is64 = (g_is64 != 0);
    for (int i = t; i < ET; i += T) {
        int s, d;
        if (i < EE) {
            s = is64 ? ei[2 * i]        : ei[i];
            d = is64 ? ei[2 * (EE + i)] : ei[EE + i];
            s = min(max(s, 0), NN - 1);
            d = min(max(d, 0), NN - 1);
        } else {
            s = d = i - EE;
        }
        int pos = atomicAdd(&g_cur[d], 1);
        g_csrc[pos] = s;
    }
}

// ---------------- SGEMM (double-buffered, BK=16) ---------------------------
template<int BM, int BN, int BK, int TM, int TN, bool A_IS_H1, bool C_IS_L1>
__global__ __launch_bounds__((BM / TM) * (BN / TN))
void sgemm2(const float* __restrict__ Ain, const float* __restrict__ B0,
            const float* __restrict__ B1, int M, int K, int ldc)
{
    constexpr int THREADS = (BM / TM) * (BN / TN);
    constexpr int A_LD = BM * BK / 4 / THREADS;
    constexpr int B_LD = BK * BN / 4 / THREADS;
    const float* __restrict__ A = A_IS_H1 ? (const float*)g_h1 : Ain;
    float* __restrict__ C = C_IS_L1 ? (float*)g_xlr1 : (float*)g_xlr2;
    const float* B = (blockIdx.y == 0) ? B0 : B1;
    const int colOff = blockIdx.y * BN;

    __shared__ float As[2][BK][BM];
    __shared__ float Bs[2][BK][BN];

    const int tid = threadIdx.x;
    const int tx = tid % (BN / TN);
    const int ty = tid / (BN / TN);
    const int rowBase = blockIdx.x * BM;

    float4 ar[A_LD], br[B_LD];

    auto loadG = [&](int kt) {
#pragma unroll
        for (int u = 0; u < A_LD; u++) {
            int i = tid + u * THREADS;
            int r  = i / (BK / 4);
            int kk = (i % (BK / 4)) * 4;
            int grow = rowBase + r;
            ar[u] = (grow < M) ? *(const float4*)(A + (size_t)grow * K + kt + kk)
                               : make_float4(0.f, 0.f, 0.f, 0.f);
        }
#pragma unroll
        for (int u = 0; u < B_LD; u++) {
            int i = tid + u * THREADS;
            int r  = i / (BN / 4);
            int cc = (i % (BN / 4)) * 4;
            br[u] = *(const float4*)(B + (size_t)(kt + r) * BN + cc);
        }
    };
    auto storeS = [&](int buf) {
#pragma unroll
        for (int u = 0; u < A_LD; u++) {
            int i = tid + u * THREADS;
            int r  = i / (BK / 4);
            int kk = (i % (BK / 4)) * 4;
            As[buf][kk + 0][r] = ar[u].x; As[buf][kk + 1][r] = ar[u].y;
            As[buf][kk + 2][r] = ar[u].z; As[buf][kk + 3][r] = ar[u].w;
        }
#pragma unroll
        for (int u = 0; u < B_LD; u++) {
            int i = tid + u * THREADS;
            int r  = i / (BN / 4);
            int cc = (i % (BN / 4)) * 4;
            *(float4*)&Bs[buf][r][cc] = br[u];
        }
    };

    float acc[TM][TN];
#pragma unroll
    for (int i = 0; i < TM; i++)
#pragma unroll
        for (int j = 0; j < TN; j++) acc[i][j] = 0.f;

    const int NT = K / BK;
    loadG(0);
    storeS(0);
    __syncthreads();

    for (int t = 0; t < NT; t++) {
        if (t + 1 < NT) loadG((t + 1) * BK);
        const int buf = t & 1;
#pragma unroll
        for (int k = 0; k < BK; k++) {
            float a[TM], b[TN];
#pragma unroll
            for (int i = 0; i < TM; i++) a[i] = As[buf][k][ty * TM + i];
#pragma unroll
            for (int j = 0; j < TN; j++) b[j] = Bs[buf][k][tx * TN + j];
#pragma unroll
            for (int i = 0; i < TM; i++)
#pragma unroll
                for (int j = 0; j < TN; j++)
                    acc[i][j] = fmaf(a[i], b[j], acc[i][j]);
        }
        if (t + 1 < NT) storeS((t + 1) & 1);
        __syncthreads();
    }

#pragma unroll
    for (int i = 0; i < TM; i++) {
        int r = rowBase + ty * TM + i;
        if (r >= M) continue;
        float* cp = C + (size_t)r * ldc + colOff + tx * TN;
#pragma unroll
        for (int j = 0; j < TN; j++) cp[j] = acc[i][j];
    }
}

// ---------------- fused GAT layer 1 (single pass, warp per dst node) -------
__global__ __launch_bounds__(256)
void gat1(const float* __restrict__ att, const float* __restrict__ b1)
{
    int w = (blockIdx.x * blockDim.x + threadIdx.x) >> 5;
    if (w >= NN) return;
    const int lane = threadIdx.x & 31;
    const int e0 = g_row[w], e1 = g_row[w + 1];

    float xr[4], a[4];
    const float* xrp = g_xlr1 + (size_t)w * 256 + 128;
#pragma unroll
    for (int i = 0; i < 4; i++) {
        xr[i] = xrp[lane + 32 * i];
        a[i]  = __ldg(&att[lane + 32 * i]);
    }

    float den0 = 0.f, den1 = 0.f;
    float out[4] = {0.f, 0.f, 0.f, 0.f};
    for (int e = e0; e < e1; e++) {
        int s = g_csrc[e];
        const float* xlp = g_xlr1 + (size_t)s * 256;
        float xl[4];
#pragma unroll
        for (int i = 0; i < 4; i++) xl[i] = xlp[lane + 32 * i];
        float p0 = 0.f, p1 = 0.f;
#pragma unroll
        for (int i = 0; i < 4; i++) {
            float m = xl[i] + xr[i];
            m = (m > 0.f) ? m : 0.2f * m;
            float v = m * a[i];
            if (i < 2) p0 += v; else p1 += v;
        }
#pragma unroll
        for (int o = 16; o > 0; o >>= 1) {
            p0 += __shfl_xor_sync(0xffffffffu, p0, o);
            p1 += __shfl_xor_sync(0xffffffffu, p1, o);
        }
        float q0 = expf(p0), q1 = expf(p1);   // identical across lanes
        den0 += q0; den1 += q1;
#pragma unroll
        for (int i = 0; i < 4; i++)
            out[i] = fmaf((i < 2) ? q0 : q1, xl[i], out[i]);
    }
    float r0 = 1.f / den0, r1 = 1.f / den1;
#pragma unroll
    for (int i = 0; i < 4; i++) {
        int c = lane + 32 * i;
        float v = out[i] * ((i < 2) ? r0 : r1) + __ldg(&b1[c]);
        g_h1[(size_t)w * 128 + c] = (v > 0.f) ? v : expm1f(v);
    }
}

// ---------------- fused GAT layer 2 + pool (single pass) -------------------
__global__ __launch_bounds__(256)
void gat2(const float* __restrict__ att, const float* __restrict__ b2)
{
    int w = (blockIdx.x * blockDim.x + threadIdx.x) >> 5;
    if (w >= NN) return;
    const int lane = threadIdx.x & 31;
    const int e0 = g_row[w], e1 = g_row[w + 1];

    float xr[2], a[2];
    const float* xrp = g_xlr2 + (size_t)w * 128 + 64;
#pragma unroll
    for (int i = 0; i < 2; i++) {
        xr[i] = xrp[lane + 32 * i];
        a[i]  = __ldg(&att[lane + 32 * i]);
    }

    float den = 0.f;
    float out[2] = {0.f, 0.f};
    for (int e = e0; e < e1; e++) {
        int s = g_csrc[e];
        const float* xlp = g_xlr2 + (size_t)s * 128;
        float xl[2];
#pragma unroll
        for (int i = 0; i < 2; i++) xl[i] = xlp[lane + 32 * i];
        float p = 0.f;
#pragma unroll
        for (int i = 0; i < 2; i++) {
            float m = xl[i] + xr[i];
            m = (m > 0.f) ? m : 0.2f * m;
            p += m * a[i];
        }
#pragma unroll
        for (int o = 16; o > 0; o >>= 1)
            p += __shfl_xor_sync(0xffffffffu, p, o);
        float q = expf(p);
        den += q;
#pragma unroll
        for (int i = 0; i < 2; i++)
            out[i] = fmaf(q, xl[i], out[i]);
    }
    float r = 1.f / den;
    const int g = g_batch[w];
#pragma unroll
    for (int i = 0; i < 2; i++) {
        int c = lane + 32 * i;
        float v = out[i] * r + __ldg(&b2[c]);
        v = (v > 0.f) ? v : expm1f(v);
        atomicAdd(&g_pool[g * 64 + c], v);
    }
}

__global__ void final_lin(const float* __restrict__ Wlin,
                          const float* __restrict__ blin,
                          float* __restrict__ out)
{
    int tid = threadIdx.x;
    if (tid >= NG * NC) return;
    int g = tid / NC, j = tid % NC;
    float inv = 1.f / fmaxf((float)g_gcnt[g], 1.f);
    float acc = blin[j];
#pragma unroll
    for (int c = 0; c < 64; c++)
        acc = fmaf(g_pool[g * 64 + c] * inv, Wlin[c * NC + j], acc);
    out[tid] = acc;
}

// ---------------- launch (ONLY kernel launches) -----------------------------
extern "C" void kernel_launch(void* const* d_in, const int* in_sizes, int n_in,
                              void* d_out, int out_size)
{
    const float* x     = (const float*)d_in[0];
    const int*   ei    = (const int*)d_in[1];
    const int*   batch = (const int*)d_in[2];
    const float* Wl1   = (const float*)d_in[3];
    const float* Wr1   = (const float*)d_in[4];
    const float* att1  = (const float*)d_in[5];
    const float* b1    = (const float*)d_in[6];
    const float* Wl2   = (const float*)d_in[7];
    const float* Wr2   = (const float*)d_in[8];
    const float* att2  = (const float*)d_in[9];
    const float* b2    = (const float*)d_in[10];
    const float* Wlin  = (const float*)d_in[11];
    const float* blin  = (const float*)d_in[12];
    float*       out   = (float*)d_out;

    const int MBLK = (NN + 127) / 128;        // 391
    const int NWBLK = (NN * 32 + 255) / 256;  // 6250 (warp per node)

    detect64<<<1, 256>>>(ei);
    zero_small<<<64, 256>>>();
    prep_idx<<<512, 256>>>(ei, batch);
    deg_partial<<<SCAN_B, 256>>>();
    scan_bsums<<<1, 256>>>();
    scan_final<<<SCAN_B, 256>>>();
    scatter_csr<<<512, 256>>>(ei);

    sgemm2<128, 128, 16, 8, 8, false, true><<<dim3(MBLK, 2), 256>>>(
        x, Wl1, Wr1, NN, 128, 256);
    gat1<<<NWBLK, 256>>>(att1, b1);

    sgemm2<128, 64, 16, 8, 4, true, false><<<dim3(MBLK, 2), 256>>>(
        nullptr, Wl2, Wr2, NN, 128, 128);
    gat2<<<NWBLK, 256>>>(att2, b2);

    final_lin<<<1, NG * NC>>>(Wlin, blin, out);
}

// round 8
// speedup vs baseline: 1.9969x; 1.0297x over previous
#include <cuda_runtime.h>

#define NN 50000
#define EE 600000
#define ET 650000   // edges + self loops
#define NG 64
#define NC 10
#define SCAN_B ((NN + 255) / 256)   // 196

typedef unsigned long long u64;
#define PACK2(d, lo, hi) \
    asm("mov.b64 %0, {%1, %2};" : "=l"(d) : "f"(lo), "f"(hi))
#define UNPACK2(lo, hi, v) \
    asm("mov.b64 {%0, %1}, %2;" : "=f"(lo), "=f"(hi) : "l"(v))
#define FMA2(d, a, b, c) \
    asm("fma.rn.f32x2 %0, %1, %2, %3;" : "=l"(d) : "l"(a), "l"(b), "l"(c))

// ---------------- scratch (device globals) ---------------------------------
__device__ float g_xlr1[(size_t)NN * 256];  // [n][0:128]=x@Wl1, [128:256]=x@Wr1
__device__ float g_h1  [(size_t)NN * 128];  // layer-1 output (elu applied)
__device__ float g_xlr2[(size_t)NN * 128];  // [n][0:64]=h1@Wl2, [64:128]=h1@Wr2
__device__ int   g_csrc[ET];                // src ids in CSR-by-dst order
__device__ int   g_deg [NN];
__device__ int   g_row [NN + 1];
__device__ int   g_cur [NN];
__device__ int   g_bsum[SCAN_B];
__device__ int   g_boff[SCAN_B];
__device__ int   g_batch[NN];
__device__ int   g_gcnt[NG];
__device__ float g_pool[NG * 64];
__device__ int   g_is64;

// ---------------- dtype detection ------------------------------------------
__global__ void detect64(const int* __restrict__ ei)
{
    __shared__ int nz;
    if (threadIdx.x == 0) nz = 0;
    __syncthreads();
    int local = 0;
    for (int i = threadIdx.x; i < 4096; i += blockDim.x)
        if (ei[2 * i + 1] != 0) local = 1;
    if (local) atomicOr(&nz, 1);
    __syncthreads();
    if (threadIdx.x == 0) g_is64 = nz ? 0 : 1;
}

__global__ void zero_small()
{
    const int T = gridDim.x * blockDim.x;
    const int t = blockIdx.x * blockDim.x + threadIdx.x;
    for (int i = t; i < NN; i += T) g_deg[i] = 0;
    for (int i = t; i < NG * 64; i += T) g_pool[i] = 0.f;
    for (int i = t; i < NG; i += T) g_gcnt[i] = 0;
}

// decode batch + histogram dst degree + graph counts
__global__ __launch_bounds__(256)
void prep_idx(const int* __restrict__ ei, const int* __restrict__ bat)
{
    __shared__ int bins[NG];
    for (int i = threadIdx.x; i < NG; i += blockDim.x) bins[i] = 0;
    __syncthreads();

    const int T = gridDim.x * blockDim.x;
    const int t = blockIdx.x * blockDim.x + threadIdx.x;
    const bool is64 = (g_is64 != 0);
    for (int i = t; i < EE; i += T) {
        int d = is64 ? ei[2 * (EE + i)] : ei[EE + i];
        d = min(max(d, 0), NN - 1);
        atomicAdd(&g_deg[d], 1);
    }
    for (int i = t; i < NN; i += T) {
        atomicAdd(&g_deg[i], 1);             // self loop
        int b = is64 ? bat[2 * i] : bat[i];
        b = min(max(b, 0), NG - 1);
        g_batch[i] = b;
        atomicAdd(&bins[b], 1);
    }
    __syncthreads();
    for (int i = threadIdx.x; i < NG; i += blockDim.x)
        if (bins[i]) atomicAdd(&g_gcnt[i], bins[i]);
}

// ---------------- decoupled exclusive scan of g_deg ------------------------
__global__ __launch_bounds__(256) void deg_partial()
{
    __shared__ int s[256];
    int idx = blockIdx.x * 256 + threadIdx.x;
    int v = (idx < NN) ? g_deg[idx] : 0;
    s[threadIdx.x] = v;
    __syncthreads();
#pragma unroll
    for (int o = 128; o > 0; o >>= 1) {
        if (threadIdx.x < o) s[threadIdx.x] += s[threadIdx.x + o];
        __syncthreads();
    }
    if (threadIdx.x == 0) g_bsum[blockIdx.x] = s[0];
}

__global__ __launch_bounds__(256) void scan_bsums()
{
    __shared__ int s[256];
    int t = threadIdx.x;
    int v = (t < SCAN_B) ? g_bsum[t] : 0;
    s[t] = v;
    __syncthreads();
#pragma unroll
    for (int o = 1; o < 256; o <<= 1) {
        int u = (t >= o) ? s[t - o] : 0;
        __syncthreads();
        s[t] += u;
        __syncthreads();
    }
    if (t < SCAN_B) g_boff[t] = s[t] - v;   // exclusive
}

__global__ __launch_bounds__(256) void scan_final()
{
    __shared__ int s[256];
    int t = threadIdx.x;
    int idx = blockIdx.x * 256 + t;
    int v = (idx < NN) ? g_deg[idx] : 0;
    s[t] = v;
    __syncthreads();
#pragma unroll
    for (int o = 1; o < 256; o <<= 1) {
        int u = (t >= o) ? s[t - o] : 0;
        __syncthreads();
        s[t] += u;
        __syncthreads();
    }
    int excl = s[t] - v + g_boff[blockIdx.x];
    if (idx < NN) { g_row[idx] = excl; g_cur[idx] = excl; }
    if (idx == NN - 1) g_row[NN] = ET;
}

__global__ void scatter_csr(const int* __restrict__ ei)
{
    const int T = gridDim.x * blockDim.x;
    const int t = blockIdx.x * blockDim.x + threadIdx.x;
    const bool is64 = (g_is64 != 0);
    for (int i = t; i < ET; i += T) {
        int s, d;
        if (i < EE) {
            s = is64 ? ei[2 * i]        : ei[i];
            d = is64 ? ei[2 * (EE + i)] : ei[EE + i];
            s = min(max(s, 0), NN - 1);
            d = min(max(d, 0), NN - 1);
        } else {
            s = d = i - EE;
        }
        int pos = atomicAdd(&g_cur[d], 1);
        g_csrc[pos] = s;
    }
}

// ---------------- SGEMM (double-buffered, f32x2 packed FMA) ----------------
template<int BM, int BN, int BK, int TM, int TN, bool A_IS_H1, bool C_IS_L1>
__global__ __launch_bounds__((BM / TM) * (BN / TN))
void sgemm2(const float* __restrict__ Ain, const float* __restrict__ B0,
            const float* __restrict__ B1, int M, int K, int ldc)
{
    constexpr int THREADS = (BM / TM) * (BN / TN);
    constexpr int A_LD = BM * BK / 4 / THREADS;
    constexpr int B_LD = BK * BN / 4 / THREADS;
    constexpr int TN2 = TN / 2;
    const float* __restrict__ A = A_IS_H1 ? (const float*)g_h1 : Ain;
    float* __restrict__ C = C_IS_L1 ? (float*)g_xlr1 : (float*)g_xlr2;
    const float* B = (blockIdx.y == 0) ? B0 : B1;
    const int colOff = blockIdx.y * BN;

    __shared__ float As[2][BK][BM];
    __shared__ float Bs[2][BK][BN];

    const int tid = threadIdx.x;
    const int tx = tid % (BN / TN);
    const int ty = tid / (BN / TN);
    const int rowBase = blockIdx.x * BM;

    float4 ar[A_LD], br[B_LD];

    auto loadG = [&](int kt) {
#pragma unroll
        for (int u = 0; u < A_LD; u++) {
            int i = tid + u * THREADS;
            int r  = i / (BK / 4);
            int kk = (i % (BK / 4)) * 4;
            int grow = rowBase + r;
            ar[u] = (grow < M) ? *(const float4*)(A + (size_t)grow * K + kt + kk)
                               : make_float4(0.f, 0.f, 0.f, 0.f);
        }
#pragma unroll
        for (int u = 0; u < B_LD; u++) {
            int i = tid + u * THREADS;
            int r  = i / (BN / 4);
            int cc = (i % (BN / 4)) * 4;
            br[u] = *(const float4*)(B + (size_t)(kt + r) * BN + cc);
        }
    };
    auto storeS = [&](int buf) {
#pragma unroll
        for (int u = 0; u < A_LD; u++) {
            int i = tid + u * THREADS;
            int r  = i / (BK / 4);
            int kk = (i % (BK / 4)) * 4;
            As[buf][kk + 0][r] = ar[u].x; As[buf][kk + 1][r] = ar[u].y;
            As[buf][kk + 2][r] = ar[u].z; As[buf][kk + 3][r] = ar[u].w;
        }
#pragma unroll
        for (int u = 0; u < B_LD; u++) {
            int i = tid + u * THREADS;
            int r  = i / (BN / 4);
            int cc = (i % (BN / 4)) * 4;
            *(float4*)&Bs[buf][r][cc] = br[u];
        }
    };

    u64 acc2[TM][TN2];
#pragma unroll
    for (int i = 0; i < TM; i++)
#pragma unroll
        for (int j = 0; j < TN2; j++) acc2[i][j] = 0ull;

    const int NT = K / BK;
    loadG(0);
    storeS(0);
    __syncthreads();

    for (int t = 0; t < NT; t++) {
        if (t + 1 < NT) loadG((t + 1) * BK);
        const int buf = t & 1;
#pragma unroll
        for (int k = 0; k < BK; k++) {
            u64 aa[TM], bb[TN2];
#pragma unroll
            for (int i = 0; i < TM; i++) {
                float av = As[buf][k][ty * TM + i];
                PACK2(aa[i], av, av);
            }
#pragma unroll
            for (int j = 0; j < TN2; j++)
                bb[j] = *(const u64*)&Bs[buf][k][tx * TN + 2 * j];
#pragma unroll
            for (int i = 0; i < TM; i++)
#pragma unroll
                for (int j = 0; j < TN2; j++)
                    FMA2(acc2[i][j], aa[i], bb[j], acc2[i][j]);
        }
        if (t + 1 < NT) storeS((t + 1) & 1);
        __syncthreads();
    }

#pragma unroll
    for (int i = 0; i < TM; i++) {
        int r = rowBase + ty * TM + i;
        if (r >= M) continue;
        float* cp = C + (size_t)r * ldc + colOff + tx * TN;
#pragma unroll
        for (int j = 0; j < TN2; j++)
            *(u64*)(cp + 2 * j) = acc2[i][j];
    }
}

// ---------------- fused GAT layer 1 (2-edge pipelined, warp per node) ------
__global__ __launch_bounds__(256)
void gat1(const float* __restrict__ att, const float* __restrict__ b1)
{
    int w = (blockIdx.x * blockDim.x + threadIdx.x) >> 5;
    if (w >= NN) return;
    const int lane = threadIdx.x & 31;
    const int e0 = g_row[w], e1 = g_row[w + 1];

    float xr[4], a[4];
    const float* xrp = g_xlr1 + (size_t)w * 256 + 128;
#pragma unroll
    for (int i = 0; i < 4; i++) {
        xr[i] = xrp[lane + 32 * i];
        a[i]  = __ldg(&att[lane + 32 * i]);
    }

    float den0 = 0.f, den1 = 0.f;
    float out[4] = {0.f, 0.f, 0.f, 0.f};

    int e = e0;
    for (; e + 2 <= e1; e += 2) {
        int s0 = g_csrc[e], s1 = g_csrc[e + 1];
        const float* pA = g_xlr1 + (size_t)s0 * 256;
        const float* pB = g_xlr1 + (size_t)s1 * 256;
        float xA[4], xB[4];
#pragma unroll
        for (int i = 0; i < 4; i++) { xA[i] = pA[lane + 32 * i]; xB[i] = pB[lane + 32 * i]; }
        float pA0 = 0.f, pA1 = 0.f, pB0 = 0.f, pB1 = 0.f;
#pragma unroll
        for (int i = 0; i < 4; i++) {
            float mA = xA[i] + xr[i]; mA = (mA > 0.f) ? mA : 0.2f * mA;
            float mB = xB[i] + xr[i]; mB = (mB > 0.f) ? mB : 0.2f * mB;
            float vA = mA * a[i], vB = mB * a[i];
            if (i < 2) { pA0 += vA; pB0 += vB; } else { pA1 += vA; pB1 += vB; }
        }
#pragma unroll
        for (int o = 16; o > 0; o >>= 1) {
            pA0 += __shfl_xor_sync(0xffffffffu, pA0, o);
            pA1 += __shfl_xor_sync(0xffffffffu, pA1, o);
            pB0 += __shfl_xor_sync(0xffffffffu, pB0, o);
            pB1 += __shfl_xor_sync(0xffffffffu, pB1, o);
        }
        float qA0 = expf(pA0), qA1 = expf(pA1);
        float qB0 = expf(pB0), qB1 = expf(pB1);
        den0 += qA0 + qB0;
        den1 += qA1 + qB1;
#pragma unroll
        for (int i = 0; i < 4; i++) {
            out[i] = fmaf((i < 2) ? qA0 : qA1, xA[i], out[i]);
            out[i] = fmaf((i < 2) ? qB0 : qB1, xB[i], out[i]);
        }
    }
    if (e < e1) {
        int s = g_csrc[e];
        const float* pA = g_xlr1 + (size_t)s * 256;
        float xA[4];
#pragma unroll
        for (int i = 0; i < 4; i++) xA[i] = pA[lane + 32 * i];
        float p0 = 0.f, p1 = 0.f;
#pragma unroll
        for (int i = 0; i < 4; i++) {
            float m = xA[i] + xr[i]; m = (m > 0.f) ? m : 0.2f * m;
            float v = m * a[i];
            if (i < 2) p0 += v; else p1 += v;
        }
#pragma unroll
        for (int o = 16; o > 0; o >>= 1) {
            p0 += __shfl_xor_sync(0xffffffffu, p0, o);
            p1 += __shfl_xor_sync(0xffffffffu, p1, o);
        }
        float q0 = expf(p0), q1 = expf(p1);
        den0 += q0; den1 += q1;
#pragma unroll
        for (int i = 0; i < 4; i++)
            out[i] = fmaf((i < 2) ? q0 : q1, xA[i], out[i]);
    }

    float r0 = 1.f / den0, r1 = 1.f / den1;
#pragma unroll
    for (int i = 0; i < 4; i++) {
        int c = lane + 32 * i;
        float v = out[i] * ((i < 2) ? r0 : r1) + __ldg(&b1[c]);
        g_h1[(size_t)w * 128 + c] = (v > 0.f) ? v : expm1f(v);
    }
}

// ---------------- fused GAT layer 2 + pool (2-edge pipelined) --------------
__global__ __launch_bounds__(256)
void gat2(const float* __restrict__ att, const float* __restrict__ b2)
{
    int w = (blockIdx.x * blockDim.x + threadIdx.x) >> 5;
    if (w >= NN) return;
    const int lane = threadIdx.x & 31;
    const int e0 = g_row[w], e1 = g_row[w + 1];

    float xr[2], a[2];
    const float* xrp = g_xlr2 + (size_t)w * 128 + 64;
#pragma unroll
    for (int i = 0; i < 2; i++) {
        xr[i] = xrp[lane + 32 * i];
        a[i]  = __ldg(&att[lane + 32 * i]);
    }

    float den = 0.f;
    float out[2] = {0.f, 0.f};

    int e = e0;
    for (; e + 2 <= e1; e += 2) {
        int s0 = g_csrc[e], s1 = g_csrc[e + 1];
        const float* pA = g_xlr2 + (size_t)s0 * 128;
        const float* pB = g_xlr2 + (size_t)s1 * 128;
        float xA[2], xB[2];
#pragma unroll
        for (int i = 0; i < 2; i++) { xA[i] = pA[lane + 32 * i]; xB[i] = pB[lane + 32 * i]; }
        float pAs = 0.f, pBs = 0.f;
#pragma unroll
        for (int i = 0; i < 2; i++) {
            float mA = xA[i] + xr[i]; mA = (mA > 0.f) ? mA : 0.2f * mA;
            float mB = xB[i] + xr[i]; mB = (mB > 0.f) ? mB : 0.2f * mB;
            pAs += mA * a[i];
            pBs += mB * a[i];
        }
#pragma unroll
        for (int o = 16; o > 0; o >>= 1) {
            pAs += __shfl_xor_sync(0xffffffffu, pAs, o);
            pBs += __shfl_xor_sync(0xffffffffu, pBs, o);
        }
        float qA = expf(pAs), qB = expf(pBs);
        den += qA + qB;
#pragma unroll
        for (int i = 0; i < 2; i++) {
            out[i] = fmaf(qA, xA[i], out[i]);
            out[i] = fmaf(qB, xB[i], out[i]);
        }
    }
    if (e < e1) {
        int s = g_csrc[e];
        const float* pA = g_xlr2 + (size_t)s * 128;
        float xA[2];
#pragma unroll
        for (int i = 0; i < 2; i++) xA[i] = pA[lane + 32 * i];
        float p = 0.f;
#pragma unroll
        for (int i = 0; i < 2; i++) {
            float m = xA[i] + xr[i]; m = (m > 0.f) ? m : 0.2f * m;
            p += m * a[i];
        }
#pragma unroll
        for (int o = 16; o > 0; o >>= 1)
            p += __shfl_xor_sync(0xffffffffu, p, o);
        float q = expf(p);
        den += q;
#pragma unroll
        for (int i = 0; i < 2; i++)
            out[i] = fmaf(q, xA[i], out[i]);
    }

    float r = 1.f / den;
    const int g = g_batch[w];
#pragma unroll
    for (int i = 0; i < 2; i++) {
        int c = lane + 32 * i;
        float v = out[i] * r + __ldg(&b2[c]);
        v = (v > 0.f) ? v : expm1f(v);
        atomicAdd(&g_pool[g * 64 + c], v);
    }
}

__global__ void final_lin(const float* __restrict__ Wlin,
                          const float* __restrict__ blin,
                          float* __restrict__ out)
{
    int tid = threadIdx.x;
    if (tid >= NG * NC) return;
    int g = tid / NC, j = tid % NC;
    float inv = 1.f / fmaxf((float)g_gcnt[g], 1.f);
    float acc = blin[j];
#pragma unroll
    for (int c = 0; c < 64; c++)
        acc = fmaf(g_pool[g * 64 + c] * inv, Wlin[c * NC + j], acc);
    out[tid] = acc;
}

// ---------------- launch (ONLY kernel launches) -----------------------------
extern "C" void kernel_launch(void* const* d_in, const int* in_sizes, int n_in,
                              void* d_out, int out_size)
{
    const float* x     = (const float*)d_in[0];
    const int*   ei    = (const int*)d_in[1];
    const int*   batch = (const int*)d_in[2];
    const float* Wl1   = (const float*)d_in[3];
    const float* Wr1   = (const float*)d_in[4];
    const float* att1  = (const float*)d_in[5];
    const float* b1    = (const float*)d_in[6];
    const float* Wl2   = (const float*)d_in[7];
    const float* Wr2   = (const float*)d_in[8];
    const float* att2  = (const float*)d_in[9];
    const float* b2    = (const float*)d_in[10];
    const float* Wlin  = (const float*)d_in[11];
    const float* blin  = (const float*)d_in[12];
    float*       out   = (float*)d_out;

    const int MBLK = (NN + 127) / 128;        // 391
    const int NWBLK = (NN * 32 + 255) / 256;  // 6250 (warp per node)

    detect64<<<1, 256>>>(ei);
    zero_small<<<64, 256>>>();
    prep_idx<<<512, 256>>>(ei, batch);
    deg_partial<<<SCAN_B, 256>>>();
    scan_bsums<<<1, 256>>>();
    scan_final<<<SCAN_B, 256>>>();
    scatter_csr<<<512, 256>>>(ei);

    sgemm2<128, 128, 16, 8, 8, false, true><<<dim3(MBLK, 2), 256>>>(
        x, Wl1, Wr1, NN, 128, 256);
    gat1<<<NWBLK, 256>>>(att1, b1);

    sgemm2<128, 64, 16, 8, 4, true, false><<<dim3(MBLK, 2), 256>>>(
        nullptr, Wl2, Wr2, NN, 128, 128);
    gat2<<<NWBLK, 256>>>(att2, b2);

    final_lin<<<1, NG * NC>>>(Wlin, blin, out);
}